// round 15
// baseline (speedup 1.0000x reference)
#include <cuda_runtime.h>
#include <math.h>

#define Hh   16
#define DKk  64
#define Dd   1024
#define Ss   2048
#define Bb   4
#define BSr  (Bb*Ss)     // 8192 rows
#define DOUTn 1024

// Scratch (device globals: no allocation allowed)
__device__ float g_Q[(size_t)Bb*Hh*Ss*DKk];
__device__ float g_K[(size_t)Bb*Hh*Ss*DKk];
__device__ float g_V[(size_t)Bb*Hh*Ss*DKk];
__device__ float g_att[(size_t)BSr*Hh*DKk];   // [B*S, H*DK] concat layout

__device__ __forceinline__ unsigned f2tf(float f){
    unsigned u; asm volatile("cvt.rna.tf32.f32 %0, %1;" : "=r"(u) : "f"(f)); return u;
}

__device__ __forceinline__ void mma8(float* c, const unsigned* a, const unsigned* b){
    asm volatile("mma.sync.aligned.m16n8k8.row.col.f32.tf32.tf32.f32 "
        "{%0,%1,%2,%3}, {%4,%5,%6,%7}, {%8,%9}, {%0,%1,%2,%3};"
        : "+f"(c[0]), "+f"(c[1]), "+f"(c[2]), "+f"(c[3])
        : "r"(a[0]), "r"(a[1]), "r"(a[2]), "r"(a[3]), "r"(b[0]), "r"(b[1]));
}

// ============================================================================
// Stage 1: QKV projection. grid = (8192/128, 3*16). Block tile 128x64, BK=32.
// 8 warps: warp_row = wid>>1 (x32 rows), warp_col = wid&1 (x32 cols).
// Register-staged double buffering: next k-tile's LDGs issue before the MMA
// chain of the current tile, hiding gmem latency behind tensor work.
// ============================================================================
__global__ __launch_bounds__(256) void qkv_kernel(
    const float* __restrict__ x,
    const float* __restrict__ Wq, const float* __restrict__ bq,
    const float* __restrict__ Wk, const float* __restrict__ bk,
    const float* __restrict__ Wv, const float* __restrict__ bv)
{
    __shared__ unsigned As[128][36];
    __shared__ unsigned Bs[64][36];

    int by = blockIdx.y;
    int mat = by >> 4, h = by & 15;
    const float* W    = (mat==0) ? Wq : (mat==1) ? Wk : Wv;
    const float* bias = (mat==0) ? bq : (mat==1) ? bk : bv;
    float* Out        = (mat==0) ? g_Q : (mat==1) ? g_K : g_V;
    W    += (size_t)h * Dd * DKk;
    bias += h * DKk;

    int r0   = blockIdx.x * 128;
    int tid  = threadIdx.x;
    int wid  = tid >> 5, lane = tid & 31;
    int g    = lane >> 2, q = lane & 3;
    int wr   = (wid >> 1) * 32;
    int wc   = (wid & 1) * 32;

    float acc[2][4][4];
    #pragma unroll
    for (int i=0;i<2;i++)
        #pragma unroll
        for (int j=0;j<4;j++)
            #pragma unroll
            for (int k=0;k<4;k++) acc[i][j][k] = 0.f;

    // prologue: stage k-tile 0 in registers
    float4 pa[4];
    float  pb[8];
    #pragma unroll
    for (int i=0;i<4;i++){
        int v = tid + i*256;
        int row = v >> 3, c4 = (v & 7) * 4;
        pa[i] = *(const float4*)(x + (size_t)(r0+row)*Dd + c4);
    }
    #pragma unroll
    for (int i=0;i<8;i++){
        int v = tid + i*256;
        int k = v >> 6, n = v & 63;
        pb[i] = W[(size_t)k*DKk + n];
    }

    for (int kb = 0; kb < Dd; kb += 32) {
        // commit staged tile to smem
        #pragma unroll
        for (int i=0;i<4;i++){
            int v = tid + i*256;
            int row = v >> 3, c4 = (v & 7) * 4;
            As[row][c4+0]=f2tf(pa[i].x); As[row][c4+1]=f2tf(pa[i].y);
            As[row][c4+2]=f2tf(pa[i].z); As[row][c4+3]=f2tf(pa[i].w);
        }
        #pragma unroll
        for (int i=0;i<8;i++){
            int v = tid + i*256;
            int k = v >> 6, n = v & 63;
            Bs[n][k] = f2tf(pb[i]);
        }
        __syncthreads();

        // prefetch next tile (independent of the MMA chain below)
        if (kb + 32 < Dd){
            #pragma unroll
            for (int i=0;i<4;i++){
                int v = tid + i*256;
                int row = v >> 3, c4 = (v & 7) * 4;
                pa[i] = *(const float4*)(x + (size_t)(r0+row)*Dd + kb + 32 + c4);
            }
            #pragma unroll
            for (int i=0;i<8;i++){
                int v = tid + i*256;
                int k = v >> 6, n = v & 63;
                pb[i] = W[(size_t)(kb+32+k)*DKk + n];
            }
        }

        #pragma unroll
        for (int ks=0; ks<4; ks++){
            unsigned a[2][4], bf[4][2];
            #pragma unroll
            for (int mt=0; mt<2; mt++){
                int r = wr + mt*16 + g;
                a[mt][0] = As[r  ][ks*8+q];
                a[mt][1] = As[r+8][ks*8+q];
                a[mt][2] = As[r  ][ks*8+q+4];
                a[mt][3] = As[r+8][ks*8+q+4];
            }
            #pragma unroll
            for (int nt=0; nt<4; nt++){
                int n = wc + nt*8 + g;
                bf[nt][0] = Bs[n][ks*8+q];
                bf[nt][1] = Bs[n][ks*8+q+4];
            }
            #pragma unroll
            for (int mt=0; mt<2; mt++)
                #pragma unroll
                for (int nt=0; nt<4; nt++)
                    mma8(acc[mt][nt], a[mt], bf[nt]);
        }
        __syncthreads();
    }

    #pragma unroll
    for (int mt=0; mt<2; mt++)
        #pragma unroll
        for (int nt=0; nt<4; nt++)
            #pragma unroll
            for (int rr=0; rr<2; rr++){
                int row = r0 + wr + mt*16 + g + rr*8;
                int b_ = row >> 11, s = row & 2047;
                int col = wc + nt*8 + q*2;
                float* dst = Out + ((size_t)(b_*Hh + h)*Ss + s)*DKk + col;
                dst[0] = acc[mt][nt][rr*2+0] + bias[col];
                dst[1] = acc[mt][nt][rr*2+1] + bias[col+1];
            }
}

// ============================================================================
// Stage 2: Flash attention. grid = (S/128, H, B), 256 thr = 8 warps,
// warp w owns q-rows [w*16, w*16+16). KV tiles of 64.
// Dynamic smem: sQ[128][68] sK[64][68] sVt[64][68] sP[128][68] (tf32 words)
// __launch_bounds__(256,2): cap regs at 128 so 2 CTAs/SM co-reside
// (smem 2x104448 < 227KB carveout) — the latency-hiding mechanism here.
// ============================================================================
#define ATT_SMEM ((size_t)(128+64+64+128)*68*4)

__global__ __launch_bounds__(256, 2) void attn_kernel()
{
    extern __shared__ unsigned sm[];
    unsigned (*sQ )[68] = (unsigned(*)[68])(sm);
    unsigned (*sK )[68] = (unsigned(*)[68])(sm + 128*68);
    unsigned (*sVt)[68] = (unsigned(*)[68])(sm + 192*68);
    unsigned (*sP )[68] = (unsigned(*)[68])(sm + 256*68);

    int qb = blockIdx.x, h = blockIdx.y, b = blockIdx.z;
    int tid = threadIdx.x, wid = tid>>5, lane = tid&31;
    int g = lane>>2, q = lane&3;
    int prow = wid*16;

    const float* Qp = g_Q + ((size_t)(b*Hh + h)*Ss + qb*128)*DKk;
    const float* Kp = g_K + (size_t)(b*Hh + h)*Ss*DKk;
    const float* Vp = g_V + (size_t)(b*Hh + h)*Ss*DKk;

    // Load Q once (128x64 = 8192 elems = 2048 float4, 8 iters x 256 thr),
    // pre-scaled by 1/sqrt(DK)=0.125 (exact power of 2).
    // FIX R12: was scalar-indexed covering only rows 0..31 (2048 elems);
    // now float4 over all 128 rows.
    #pragma unroll
    for (int i=0;i<8;i++){
        int v = tid + i*256;           // v < 2048 float4s
        int row = v >> 4, c4 = (v & 15) * 4;
        float4 f = *(const float4*)(Qp + (size_t)row*DKk + c4);
        sQ[row][c4+0] = f2tf(f.x * 0.125f);
        sQ[row][c4+1] = f2tf(f.y * 0.125f);
        sQ[row][c4+2] = f2tf(f.z * 0.125f);
        sQ[row][c4+3] = f2tf(f.w * 0.125f);
    }

    float m0 = -1e30f, m1 = -1e30f, l0 = 0.f, l1 = 0.f;
    float o[8][4];
    #pragma unroll
    for (int nt=0;nt<8;nt++)
        #pragma unroll
        for (int j=0;j<4;j++) o[nt][j] = 0.f;

    for (int kv = 0; kv < Ss; kv += 64){
        __syncthreads();   // sK/sVt reuse fence (also orders sQ on iter 0)

        const float* Kt = Kp + (size_t)kv*DKk;
        const float* Vg = Vp + (size_t)kv*DKk;
        #pragma unroll
        for (int i=0;i<4;i++){          // K tile 64x64 via float4
            int v = tid + i*256;
            int row = v >> 4, c4 = (v & 15)*4;
            float4 f = *(const float4*)(Kt + row*DKk + c4);
            sK[row][c4+0]=f2tf(f.x); sK[row][c4+1]=f2tf(f.y);
            sK[row][c4+2]=f2tf(f.z); sK[row][c4+3]=f2tf(f.w);
        }
        #pragma unroll
        for (int i=0;i<16;i++){         // V tile 64x64 transposed -> sVt[dk][kv]
            int v = tid + i*256;
            int row = v >> 6, c = v & 63;
            sVt[c][row] = f2tf(Vg[(size_t)row*DKk + c]);
        }
        __syncthreads();

        // ---- scores: S[16 x 64] = Q_warp[16,64] * K^T ----
        float s[8][4];
        #pragma unroll
        for (int nt=0;nt<8;nt++)
            #pragma unroll
            for (int j=0;j<4;j++) s[nt][j]=0.f;

        #pragma unroll
        for (int ks=0;ks<8;ks++){
            unsigned a[4];
            int r = prow + g;
            a[0]=sQ[r  ][ks*8+q];  a[1]=sQ[r+8][ks*8+q];
            a[2]=sQ[r  ][ks*8+q+4];a[3]=sQ[r+8][ks*8+q+4];
            #pragma unroll
            for (int nt=0;nt<8;nt++){
                unsigned bf[2];
                bf[0]=sK[nt*8+g][ks*8+q];
                bf[1]=sK[nt*8+g][ks*8+q+4];
                mma8(s[nt], a, bf);
            }
        }

        // ---- online softmax (rows g and g+8, stats per 4-lane group) ----
        float mx0 = -1e30f, mx1 = -1e30f;
        #pragma unroll
        for (int nt=0;nt<8;nt++){
            mx0 = fmaxf(mx0, fmaxf(s[nt][0], s[nt][1]));
            mx1 = fmaxf(mx1, fmaxf(s[nt][2], s[nt][3]));
        }
        mx0 = fmaxf(mx0, __shfl_xor_sync(0xffffffff, mx0, 1));
        mx0 = fmaxf(mx0, __shfl_xor_sync(0xffffffff, mx0, 2));
        mx1 = fmaxf(mx1, __shfl_xor_sync(0xffffffff, mx1, 1));
        mx1 = fmaxf(mx1, __shfl_xor_sync(0xffffffff, mx1, 2));

        float nm0 = fmaxf(m0, mx0), nm1 = fmaxf(m1, mx1);
        float al0 = __expf(m0 - nm0), al1 = __expf(m1 - nm1);
        m0 = nm0; m1 = nm1;

        float sum0 = 0.f, sum1 = 0.f;
        #pragma unroll
        for (int nt=0;nt<8;nt++){
            float p00 = __expf(s[nt][0]-m0), p01 = __expf(s[nt][1]-m0);
            float p10 = __expf(s[nt][2]-m1), p11 = __expf(s[nt][3]-m1);
            sum0 += p00 + p01; sum1 += p10 + p11;
            int col = nt*8 + 2*q;
            sP[prow+g  ][col] = f2tf(p00); sP[prow+g  ][col+1] = f2tf(p01);
            sP[prow+g+8][col] = f2tf(p10); sP[prow+g+8][col+1] = f2tf(p11);
        }
        sum0 += __shfl_xor_sync(0xffffffff, sum0, 1);
        sum0 += __shfl_xor_sync(0xffffffff, sum0, 2);
        sum1 += __shfl_xor_sync(0xffffffff, sum1, 1);
        sum1 += __shfl_xor_sync(0xffffffff, sum1, 2);
        l0 = l0*al0 + sum0;
        l1 = l1*al1 + sum1;

        #pragma unroll
        for (int nt=0;nt<8;nt++){
            o[nt][0]*=al0; o[nt][1]*=al0; o[nt][2]*=al1; o[nt][3]*=al1;
        }
        __syncwarp();   // sP visible across the warp (rows are warp-private)

        // ---- O += P[16,64] * V[64,64] ----
        #pragma unroll
        for (int ks=0;ks<8;ks++){
            unsigned a[4];
            int r = prow + g;
            a[0]=sP[r  ][ks*8+q];  a[1]=sP[r+8][ks*8+q];
            a[2]=sP[r  ][ks*8+q+4];a[3]=sP[r+8][ks*8+q+4];
            #pragma unroll
            for (int nt=0;nt<8;nt++){
                unsigned bf[2];
                bf[0]=sVt[nt*8+g][ks*8+q];
                bf[1]=sVt[nt*8+g][ks*8+q+4];
                mma8(o[nt], a, bf);
            }
        }
    }

    // epilogue -> g_att[b*S + s][h*64 + col]
    float inv0 = 1.f / l0, inv1 = 1.f / l1;
    int s0 = qb*128 + prow + g;
    #pragma unroll
    for (int nt=0;nt<8;nt++){
        int col = h*64 + nt*8 + 2*q;
        float* d0 = g_att + (size_t)(b*Ss + s0    )*(Hh*DKk) + col;
        float* d1 = g_att + (size_t)(b*Ss + s0 + 8)*(Hh*DKk) + col;
        d0[0] = o[nt][0]*inv0; d0[1] = o[nt][1]*inv0;
        d1[0] = o[nt][2]*inv1; d1[1] = o[nt][3]*inv1;
    }
}

// ============================================================================
// Stage 3: output projection. grid = (8192/128, 1024/64). Same tiling as QKV,
// same register-staged double buffering.
// ============================================================================
__global__ __launch_bounds__(256) void oproj_kernel(
    const float* __restrict__ Wo, const float* __restrict__ bo,
    float* __restrict__ out)
{
    __shared__ unsigned As[128][36];
    __shared__ unsigned Bs[64][36];

    int cb = blockIdx.y * 64;
    int r0 = blockIdx.x * 128;
    int tid = threadIdx.x;
    int wid = tid >> 5, lane = tid & 31;
    int g = lane >> 2, q = lane & 3;
    int wr = (wid >> 1) * 32;
    int wc = (wid & 1) * 32;

    float acc[2][4][4];
    #pragma unroll
    for (int i=0;i<2;i++)
        #pragma unroll
        for (int j=0;j<4;j++)
            #pragma unroll
            for (int k=0;k<4;k++) acc[i][j][k]=0.f;

    // prologue: stage k-tile 0 in registers
    float4 pa[4];
    float  pb[8];
    #pragma unroll
    for (int i=0;i<4;i++){
        int v = tid + i*256;
        int row = v >> 3, c4 = (v & 7) * 4;
        pa[i] = *(const float4*)(g_att + (size_t)(r0+row)*(Hh*DKk) + c4);
    }
    #pragma unroll
    for (int i=0;i<8;i++){
        int v = tid + i*256;
        int k = v >> 6, n = v & 63;
        pb[i] = Wo[(size_t)k*DOUTn + cb + n];
    }

    for (int kb = 0; kb < Hh*DKk; kb += 32) {
        #pragma unroll
        for (int i=0;i<4;i++){
            int v = tid + i*256;
            int row = v >> 3, c4 = (v & 7) * 4;
            As[row][c4+0]=f2tf(pa[i].x); As[row][c4+1]=f2tf(pa[i].y);
            As[row][c4+2]=f2tf(pa[i].z); As[row][c4+3]=f2tf(pa[i].w);
        }
        #pragma unroll
        for (int i=0;i<8;i++){
            int v = tid + i*256;
            int k = v >> 6, n = v & 63;
            Bs[n][k] = f2tf(pb[i]);
        }
        __syncthreads();

        if (kb + 32 < Hh*DKk){
            #pragma unroll
            for (int i=0;i<4;i++){
                int v = tid + i*256;
                int row = v >> 3, c4 = (v & 7) * 4;
                pa[i] = *(const float4*)(g_att + (size_t)(r0+row)*(Hh*DKk) + kb + 32 + c4);
            }
            #pragma unroll
            for (int i=0;i<8;i++){
                int v = tid + i*256;
                int k = v >> 6, n = v & 63;
                pb[i] = Wo[(size_t)(kb+32+k)*DOUTn + cb + n];
            }
        }

        #pragma unroll
        for (int ks=0; ks<4; ks++){
            unsigned a[2][4], bf[4][2];
            #pragma unroll
            for (int mt=0; mt<2; mt++){
                int r = wr + mt*16 + g;
                a[mt][0] = As[r  ][ks*8+q];
                a[mt][1] = As[r+8][ks*8+q];
                a[mt][2] = As[r  ][ks*8+q+4];
                a[mt][3] = As[r+8][ks*8+q+4];
            }
            #pragma unroll
            for (int nt=0; nt<4; nt++){
                int n = wc + nt*8 + g;
                bf[nt][0] = Bs[n][ks*8+q];
                bf[nt][1] = Bs[n][ks*8+q+4];
            }
            #pragma unroll
            for (int mt=0; mt<2; mt++)
                #pragma unroll
                for (int nt=0; nt<4; nt++)
                    mma8(acc[mt][nt], a[mt], bf[nt]);
        }
        __syncthreads();
    }

    #pragma unroll
    for (int mt=0; mt<2; mt++)
        #pragma unroll
        for (int nt=0; nt<4; nt++)
            #pragma unroll
            for (int rr=0; rr<2; rr++){
                int row = r0 + wr + mt*16 + g + rr*8;
                int col = cb + wc + nt*8 + q*2;
                out[(size_t)row*DOUTn + col    ] = acc[mt][nt][rr*2+0] + bo[col];
                out[(size_t)row*DOUTn + col + 1] = acc[mt][nt][rr*2+1] + bo[col+1];
            }
}

// ============================================================================
extern "C" void kernel_launch(void* const* d_in, const int* in_sizes, int n_in,
                              void* d_out, int out_size)
{
    (void)in_sizes; (void)n_in; (void)out_size;
    const float* x  = (const float*)d_in[0];
    const float* Wq = (const float*)d_in[1];
    const float* bq = (const float*)d_in[2];
    const float* Wk = (const float*)d_in[3];
    const float* bk = (const float*)d_in[4];
    const float* Wv = (const float*)d_in[5];
    const float* bv = (const float*)d_in[6];
    const float* Wo = (const float*)d_in[7];
    const float* bo = (const float*)d_in[8];
    float* out = (float*)d_out;

    cudaFuncSetAttribute(attn_kernel,
        cudaFuncAttributeMaxDynamicSharedMemorySize, (int)ATT_SMEM);

    qkv_kernel<<<dim3(BSr/128, 48), 256>>>(x, Wq, bq, Wk, bk, Wv, bv);
    attn_kernel<<<dim3(Ss/128, Hh, Bb), 256, ATT_SMEM>>>();
    oproj_kernel<<<dim3(BSr/128, DOUTn/64), 256>>>(Wo, bo, out);
}

// round 17
// speedup vs baseline: 1.0478x; 1.0478x over previous
#include <cuda_runtime.h>
#include <math.h>

#define Hh   16
#define DKk  64
#define Dd   1024
#define Ss   2048
#define Bb   4
#define BSr  (Bb*Ss)     // 8192 rows
#define DOUTn 1024

// Scratch (device globals: no allocation allowed)
__device__ float g_Q[(size_t)Bb*Hh*Ss*DKk];
__device__ float g_K[(size_t)Bb*Hh*Ss*DKk];
__device__ float g_V[(size_t)Bb*Hh*Ss*DKk];
__device__ float g_att[(size_t)BSr*Hh*DKk];   // [B*S, H*DK] concat layout

__device__ __forceinline__ unsigned f2tf(float f){
    unsigned u; asm volatile("cvt.rna.tf32.f32 %0, %1;" : "=r"(u) : "f"(f)); return u;
}

__device__ __forceinline__ void mma8(float* c, const unsigned* a, const unsigned* b){
    asm volatile("mma.sync.aligned.m16n8k8.row.col.f32.tf32.tf32.f32 "
        "{%0,%1,%2,%3}, {%4,%5,%6,%7}, {%8,%9}, {%0,%1,%2,%3};"
        : "+f"(c[0]), "+f"(c[1]), "+f"(c[2]), "+f"(c[3])
        : "r"(a[0]), "r"(a[1]), "r"(a[2]), "r"(a[3]), "r"(b[0]), "r"(b[1]));
}

// ============================================================================
// Stage 1: FUSED QKV projection. grid = (8192/128, 16 heads). One CTA computes
// Q, K and V 128x64 tiles for its head: the x tile (A) is loaded to smem ONCE
// and its fragments are reused across the 3 weight matrices, cutting L1/smem
// traffic ~1.57x (R15 ncu: qkv was L1-bound at 75.4%).
// Per ks: 8 A-LDS (reused 3x) + 24 B-LDS feed 24 MMAs (171B/MMA vs 256B).
// acc = 3x32 floats -> ~180 regs -> 1 CTA/SM; L1 BW is the binding resource,
// 8 warps saturate it.
// ============================================================================
__global__ __launch_bounds__(256) void qkv_kernel(
    const float* __restrict__ x,
    const float* __restrict__ Wq, const float* __restrict__ bq,
    const float* __restrict__ Wk, const float* __restrict__ bk,
    const float* __restrict__ Wv, const float* __restrict__ bv)
{
    __shared__ unsigned As[128][36];
    __shared__ unsigned Bs[3][64][36];

    int h = blockIdx.y;
    const float* Wm[3];
    Wm[0] = Wq + (size_t)h * Dd * DKk;
    Wm[1] = Wk + (size_t)h * Dd * DKk;
    Wm[2] = Wv + (size_t)h * Dd * DKk;

    int r0   = blockIdx.x * 128;
    int tid  = threadIdx.x;
    int wid  = tid >> 5, lane = tid & 31;
    int g    = lane >> 2, q = lane & 3;
    int wr   = (wid >> 1) * 32;
    int wc   = (wid & 1) * 32;

    float acc[3][2][4][4];
    #pragma unroll
    for (int m=0;m<3;m++)
        #pragma unroll
        for (int i=0;i<2;i++)
            #pragma unroll
            for (int j=0;j<4;j++)
                #pragma unroll
                for (int k=0;k<4;k++) acc[m][i][j][k] = 0.f;

    // prologue: stage k-tile 0 in registers
    float4 pa[4];
    float  pb[3][8];
    #pragma unroll
    for (int i=0;i<4;i++){
        int v = tid + i*256;
        int row = v >> 3, c4 = (v & 7) * 4;
        pa[i] = *(const float4*)(x + (size_t)(r0+row)*Dd + c4);
    }
    #pragma unroll
    for (int m=0;m<3;m++)
        #pragma unroll
        for (int i=0;i<8;i++){
            int v = tid + i*256;
            int k = v >> 6, n = v & 63;
            pb[m][i] = Wm[m][(size_t)k*DKk + n];
        }

    for (int kb = 0; kb < Dd; kb += 32) {
        // commit staged tiles to smem
        #pragma unroll
        for (int i=0;i<4;i++){
            int v = tid + i*256;
            int row = v >> 3, c4 = (v & 7) * 4;
            As[row][c4+0]=f2tf(pa[i].x); As[row][c4+1]=f2tf(pa[i].y);
            As[row][c4+2]=f2tf(pa[i].z); As[row][c4+3]=f2tf(pa[i].w);
        }
        #pragma unroll
        for (int m=0;m<3;m++)
            #pragma unroll
            for (int i=0;i<8;i++){
                int v = tid + i*256;
                int k = v >> 6, n = v & 63;
                Bs[m][n][k] = f2tf(pb[m][i]);
            }
        __syncthreads();

        // prefetch next k-tile (independent of the MMA chain below)
        if (kb + 32 < Dd){
            #pragma unroll
            for (int i=0;i<4;i++){
                int v = tid + i*256;
                int row = v >> 3, c4 = (v & 7) * 4;
                pa[i] = *(const float4*)(x + (size_t)(r0+row)*Dd + kb + 32 + c4);
            }
            #pragma unroll
            for (int m=0;m<3;m++)
                #pragma unroll
                for (int i=0;i<8;i++){
                    int v = tid + i*256;
                    int k = v >> 6, n = v & 63;
                    pb[m][i] = Wm[m][(size_t)(kb+32+k)*DKk + n];
                }
        }

        #pragma unroll
        for (int ks=0; ks<4; ks++){
            unsigned a[2][4];
            #pragma unroll
            for (int mt=0; mt<2; mt++){
                int r = wr + mt*16 + g;
                a[mt][0] = As[r  ][ks*8+q];
                a[mt][1] = As[r+8][ks*8+q];
                a[mt][2] = As[r  ][ks*8+q+4];
                a[mt][3] = As[r+8][ks*8+q+4];
            }
            #pragma unroll
            for (int m=0;m<3;m++){
                unsigned bf[4][2];
                #pragma unroll
                for (int nt=0; nt<4; nt++){
                    int n = wc + nt*8 + g;
                    bf[nt][0] = Bs[m][n][ks*8+q];
                    bf[nt][1] = Bs[m][n][ks*8+q+4];
                }
                #pragma unroll
                for (int mt=0; mt<2; mt++)
                    #pragma unroll
                    for (int nt=0; nt<4; nt++)
                        mma8(acc[m][mt][nt], a[mt], bf[nt]);
            }
        }
        __syncthreads();
    }

    // epilogue: write Q, K, V tiles
    #pragma unroll
    for (int m=0;m<3;m++){
        float* Out = (m==0) ? g_Q : (m==1) ? g_K : g_V;
        const float* bias = ((m==0) ? bq : (m==1) ? bk : bv) + h * DKk;
        #pragma unroll
        for (int mt=0; mt<2; mt++)
            #pragma unroll
            for (int nt=0; nt<4; nt++)
                #pragma unroll
                for (int rr=0; rr<2; rr++){
                    int row = r0 + wr + mt*16 + g + rr*8;
                    int b_ = row >> 11, s = row & 2047;
                    int col = wc + nt*8 + q*2;
                    float* dst = Out + ((size_t)(b_*Hh + h)*Ss + s)*DKk + col;
                    dst[0] = acc[m][mt][nt][rr*2+0] + bias[col];
                    dst[1] = acc[m][mt][nt][rr*2+1] + bias[col+1];
                }
    }
}

// ============================================================================
// Stage 2: Flash attention. grid = (S/128, H, B), 256 thr = 8 warps,
// warp w owns q-rows [w*16, w*16+16). KV tiles of 64.
// Dynamic smem: sQ[128][68] sK[64][68] sVt[64][68] sP[128][68] (tf32 words)
// __launch_bounds__(256,2): cap regs at 128 so 2 CTAs/SM co-reside
// (smem 2x104448 < 227KB carveout) — the latency-hiding mechanism here.
// ============================================================================
#define ATT_SMEM ((size_t)(128+64+64+128)*68*4)

__global__ __launch_bounds__(256, 2) void attn_kernel()
{
    extern __shared__ unsigned sm[];
    unsigned (*sQ )[68] = (unsigned(*)[68])(sm);
    unsigned (*sK )[68] = (unsigned(*)[68])(sm + 128*68);
    unsigned (*sVt)[68] = (unsigned(*)[68])(sm + 192*68);
    unsigned (*sP )[68] = (unsigned(*)[68])(sm + 256*68);

    int qb = blockIdx.x, h = blockIdx.y, b = blockIdx.z;
    int tid = threadIdx.x, wid = tid>>5, lane = tid&31;
    int g = lane>>2, q = lane&3;
    int prow = wid*16;

    const float* Qp = g_Q + ((size_t)(b*Hh + h)*Ss + qb*128)*DKk;
    const float* Kp = g_K + (size_t)(b*Hh + h)*Ss*DKk;
    const float* Vp = g_V + (size_t)(b*Hh + h)*Ss*DKk;

    // Load Q once (128x64 = 2048 float4), pre-scaled by 1/sqrt(DK)=0.125
    #pragma unroll
    for (int i=0;i<8;i++){
        int v = tid + i*256;
        int row = v >> 4, c4 = (v & 15) * 4;
        float4 f = *(const float4*)(Qp + (size_t)row*DKk + c4);
        sQ[row][c4+0] = f2tf(f.x * 0.125f);
        sQ[row][c4+1] = f2tf(f.y * 0.125f);
        sQ[row][c4+2] = f2tf(f.z * 0.125f);
        sQ[row][c4+3] = f2tf(f.w * 0.125f);
    }

    float m0 = -1e30f, m1 = -1e30f, l0 = 0.f, l1 = 0.f;
    float o[8][4];
    #pragma unroll
    for (int nt=0;nt<8;nt++)
        #pragma unroll
        for (int j=0;j<4;j++) o[nt][j] = 0.f;

    for (int kv = 0; kv < Ss; kv += 64){
        __syncthreads();   // sK/sVt reuse fence (also orders sQ on iter 0)

        const float* Kt = Kp + (size_t)kv*DKk;
        const float* Vg = Vp + (size_t)kv*DKk;
        #pragma unroll
        for (int i=0;i<4;i++){          // K tile 64x64 via float4
            int v = tid + i*256;
            int row = v >> 4, c4 = (v & 15)*4;
            float4 f = *(const float4*)(Kt + row*DKk + c4);
            sK[row][c4+0]=f2tf(f.x); sK[row][c4+1]=f2tf(f.y);
            sK[row][c4+2]=f2tf(f.z); sK[row][c4+3]=f2tf(f.w);
        }
        #pragma unroll
        for (int i=0;i<16;i++){         // V tile 64x64 transposed -> sVt[dk][kv]
            int v = tid + i*256;
            int row = v >> 6, c = v & 63;
            sVt[c][row] = f2tf(Vg[(size_t)row*DKk + c]);
        }
        __syncthreads();

        // ---- scores: S[16 x 64] = Q_warp[16,64] * K^T ----
        float s[8][4];
        #pragma unroll
        for (int nt=0;nt<8;nt++)
            #pragma unroll
            for (int j=0;j<4;j++) s[nt][j]=0.f;

        #pragma unroll
        for (int ks=0;ks<8;ks++){
            unsigned a[4];
            int r = prow + g;
            a[0]=sQ[r  ][ks*8+q];  a[1]=sQ[r+8][ks*8+q];
            a[2]=sQ[r  ][ks*8+q+4];a[3]=sQ[r+8][ks*8+q+4];
            #pragma unroll
            for (int nt=0;nt<8;nt++){
                unsigned bf[2];
                bf[0]=sK[nt*8+g][ks*8+q];
                bf[1]=sK[nt*8+g][ks*8+q+4];
                mma8(s[nt], a, bf);
            }
        }

        // ---- online softmax (rows g and g+8, stats per 4-lane group) ----
        float mx0 = -1e30f, mx1 = -1e30f;
        #pragma unroll
        for (int nt=0;nt<8;nt++){
            mx0 = fmaxf(mx0, fmaxf(s[nt][0], s[nt][1]));
            mx1 = fmaxf(mx1, fmaxf(s[nt][2], s[nt][3]));
        }
        mx0 = fmaxf(mx0, __shfl_xor_sync(0xffffffff, mx0, 1));
        mx0 = fmaxf(mx0, __shfl_xor_sync(0xffffffff, mx0, 2));
        mx1 = fmaxf(mx1, __shfl_xor_sync(0xffffffff, mx1, 1));
        mx1 = fmaxf(mx1, __shfl_xor_sync(0xffffffff, mx1, 2));

        float nm0 = fmaxf(m0, mx0), nm1 = fmaxf(m1, mx1);
        float al0 = __expf(m0 - nm0), al1 = __expf(m1 - nm1);
        m0 = nm0; m1 = nm1;

        float sum0 = 0.f, sum1 = 0.f;
        #pragma unroll
        for (int nt=0;nt<8;nt++){
            float p00 = __expf(s[nt][0]-m0), p01 = __expf(s[nt][1]-m0);
            float p10 = __expf(s[nt][2]-m1), p11 = __expf(s[nt][3]-m1);
            sum0 += p00 + p01; sum1 += p10 + p11;
            int col = nt*8 + 2*q;
            sP[prow+g  ][col] = f2tf(p00); sP[prow+g  ][col+1] = f2tf(p01);
            sP[prow+g+8][col] = f2tf(p10); sP[prow+g+8][col+1] = f2tf(p11);
        }
        sum0 += __shfl_xor_sync(0xffffffff, sum0, 1);
        sum0 += __shfl_xor_sync(0xffffffff, sum0, 2);
        sum1 += __shfl_xor_sync(0xffffffff, sum1, 1);
        sum1 += __shfl_xor_sync(0xffffffff, sum1, 2);
        l0 = l0*al0 + sum0;
        l1 = l1*al1 + sum1;

        #pragma unroll
        for (int nt=0;nt<8;nt++){
            o[nt][0]*=al0; o[nt][1]*=al0; o[nt][2]*=al1; o[nt][3]*=al1;
        }
        __syncwarp();   // sP visible across the warp (rows are warp-private)

        // ---- O += P[16,64] * V[64,64] ----
        #pragma unroll
        for (int ks=0;ks<8;ks++){
            unsigned a[4];
            int r = prow + g;
            a[0]=sP[r  ][ks*8+q];  a[1]=sP[r+8][ks*8+q];
            a[2]=sP[r  ][ks*8+q+4];a[3]=sP[r+8][ks*8+q+4];
            #pragma unroll
            for (int nt=0;nt<8;nt++){
                unsigned bf[2];
                bf[0]=sVt[nt*8+g][ks*8+q];
                bf[1]=sVt[nt*8+g][ks*8+q+4];
                mma8(o[nt], a, bf);
            }
        }
    }

    // epilogue -> g_att[b*S + s][h*64 + col]
    float inv0 = 1.f / l0, inv1 = 1.f / l1;
    int s0 = qb*128 + prow + g;
    #pragma unroll
    for (int nt=0;nt<8;nt++){
        int col = h*64 + nt*8 + 2*q;
        float* d0 = g_att + (size_t)(b*Ss + s0    )*(Hh*DKk) + col;
        float* d1 = g_att + (size_t)(b*Ss + s0 + 8)*(Hh*DKk) + col;
        d0[0] = o[nt][0]*inv0; d0[1] = o[nt][1]*inv0;
        d1[0] = o[nt][2]*inv1; d1[1] = o[nt][3]*inv1;
    }
}

// ============================================================================
// Stage 3: output projection. grid = (8192/128, 1024/64). Same tiling as the
// old qkv, register-staged double buffering.
// ============================================================================
__global__ __launch_bounds__(256) void oproj_kernel(
    const float* __restrict__ Wo, const float* __restrict__ bo,
    float* __restrict__ out)
{
    __shared__ unsigned As[128][36];
    __shared__ unsigned Bs[64][36];

    int cb = blockIdx.y * 64;
    int r0 = blockIdx.x * 128;
    int tid = threadIdx.x;
    int wid = tid >> 5, lane = tid & 31;
    int g = lane >> 2, q = lane & 3;
    int wr = (wid >> 1) * 32;
    int wc = (wid & 1) * 32;

    float acc[2][4][4];
    #pragma unroll
    for (int i=0;i<2;i++)
        #pragma unroll
        for (int j=0;j<4;j++)
            #pragma unroll
            for (int k=0;k<4;k++) acc[i][j][k]=0.f;

    // prologue: stage k-tile 0 in registers
    float4 pa[4];
    float  pb[8];
    #pragma unroll
    for (int i=0;i<4;i++){
        int v = tid + i*256;
        int row = v >> 3, c4 = (v & 7) * 4;
        pa[i] = *(const float4*)(g_att + (size_t)(r0+row)*(Hh*DKk) + c4);
    }
    #pragma unroll
    for (int i=0;i<8;i++){
        int v = tid + i*256;
        int k = v >> 6, n = v & 63;
        pb[i] = Wo[(size_t)k*DOUTn + cb + n];
    }

    for (int kb = 0; kb < Hh*DKk; kb += 32) {
        #pragma unroll
        for (int i=0;i<4;i++){
            int v = tid + i*256;
            int row = v >> 3, c4 = (v & 7) * 4;
            As[row][c4+0]=f2tf(pa[i].x); As[row][c4+1]=f2tf(pa[i].y);
            As[row][c4+2]=f2tf(pa[i].z); As[row][c4+3]=f2tf(pa[i].w);
        }
        #pragma unroll
        for (int i=0;i<8;i++){
            int v = tid + i*256;
            int k = v >> 6, n = v & 63;
            Bs[n][k] = f2tf(pb[i]);
        }
        __syncthreads();

        if (kb + 32 < Hh*DKk){
            #pragma unroll
            for (int i=0;i<4;i++){
                int v = tid + i*256;
                int row = v >> 3, c4 = (v & 7) * 4;
                pa[i] = *(const float4*)(g_att + (size_t)(r0+row)*(Hh*DKk) + kb + 32 + c4);
            }
            #pragma unroll
            for (int i=0;i<8;i++){
                int v = tid + i*256;
                int k = v >> 6, n = v & 63;
                pb[i] = Wo[(size_t)(kb+32+k)*DOUTn + cb + n];
            }
        }

        #pragma unroll
        for (int ks=0; ks<4; ks++){
            unsigned a[2][4], bf[4][2];
            #pragma unroll
            for (int mt=0; mt<2; mt++){
                int r = wr + mt*16 + g;
                a[mt][0] = As[r  ][ks*8+q];
                a[mt][1] = As[r+8][ks*8+q];
                a[mt][2] = As[r  ][ks*8+q+4];
                a[mt][3] = As[r+8][ks*8+q+4];
            }
            #pragma unroll
            for (int nt=0; nt<4; nt++){
                int n = wc + nt*8 + g;
                bf[nt][0] = Bs[n][ks*8+q];
                bf[nt][1] = Bs[n][ks*8+q+4];
            }
            #pragma unroll
            for (int mt=0; mt<2; mt++)
                #pragma unroll
                for (int nt=0; nt<4; nt++)
                    mma8(acc[mt][nt], a[mt], bf[nt]);
        }
        __syncthreads();
    }

    #pragma unroll
    for (int mt=0; mt<2; mt++)
        #pragma unroll
        for (int nt=0; nt<4; nt++)
            #pragma unroll
            for (int rr=0; rr<2; rr++){
                int row = r0 + wr + mt*16 + g + rr*8;
                int col = cb + wc + nt*8 + q*2;
                out[(size_t)row*DOUTn + col    ] = acc[mt][nt][rr*2+0] + bo[col];
                out[(size_t)row*DOUTn + col + 1] = acc[mt][nt][rr*2+1] + bo[col+1];
            }
}

// ============================================================================
extern "C" void kernel_launch(void* const* d_in, const int* in_sizes, int n_in,
                              void* d_out, int out_size)
{
    (void)in_sizes; (void)n_in; (void)out_size;
    const float* x  = (const float*)d_in[0];
    const float* Wq = (const float*)d_in[1];
    const float* bq = (const float*)d_in[2];
    const float* Wk = (const float*)d_in[3];
    const float* bk = (const float*)d_in[4];
    const float* Wv = (const float*)d_in[5];
    const float* bv = (const float*)d_in[6];
    const float* Wo = (const float*)d_in[7];
    const float* bo = (const float*)d_in[8];
    float* out = (float*)d_out;

    cudaFuncSetAttribute(attn_kernel,
        cudaFuncAttributeMaxDynamicSharedMemorySize, (int)ATT_SMEM);

    qkv_kernel<<<dim3(BSr/128, Hh), 256>>>(x, Wq, bq, Wk, bk, Wv, bv);
    attn_kernel<<<dim3(Ss/128, Hh, Bb), 256, ATT_SMEM>>>();
    oproj_kernel<<<dim3(BSr/128, DOUTn/64), 256>>>(Wo, bo, out);
}